// round 14
// baseline (speedup 1.0000x reference)
#include <cuda_runtime.h>
#include <cuda_bf16.h>

#define N_NODES  50000
#define N_EDGESC 1600000
#define ET       1650000            // edges + self loops
#define F        128
#define FE       32
#define NG       512
#define NC       10
#define SLOPE    0.2f
#define SCAN_NB  ((N_NODES + 1023) / 1024)   // 49

typedef unsigned long long u64;

// ---------------- f32x2 helpers (Blackwell packed fp32) ----------------------
__device__ __forceinline__ u64 pack2(float x, float y) {
    u64 r; asm("mov.b64 %0, {%1, %2};" : "=l"(r) : "f"(x), "f"(y)); return r;
}
__device__ __forceinline__ float2 unpack2(u64 v) {
    float2 f; asm("mov.b64 {%0, %1}, %2;" : "=f"(f.x), "=f"(f.y) : "l"(v)); return f;
}
__device__ __forceinline__ u64 ffma2(u64 a, u64 b, u64 c) {
    u64 d; asm("fma.rn.f32x2 %0, %1, %2, %3;" : "=l"(d) : "l"(a), "l"(b), "l"(c)); return d;
}

// ---------------- scratch (device globals: allocation-free rule) -------------
__device__ float g_eas[(size_t)ET * FE];   // edge attrs in CSR slot order (211MB)
__device__ float g_score[ET];
__device__ float g_xl[(size_t)N_NODES * F];
__device__ float g_xr[(size_t)N_NODES * F];
__device__ float g_hA[(size_t)N_NODES * F];
__device__ float g_hB[(size_t)N_NODES * F];
__device__ int   g_deg[N_NODES];
__device__ int   g_rowptr[N_NODES + 1];
__device__ int   g_cnt[N_NODES];
__device__ int   g_srcs[ET];
__device__ int   g_dsts[ET];
__device__ int   g_slot[N_EDGESC];
__device__ int   g_bsum[64];
__device__ int   g_boff[64];
__device__ int   g_gptr[NG + 1];
__device__ float g_pool[NG * F];
__device__ int   g_is64;

// ---------------- index dtype handling --------------------------------------
__device__ __forceinline__ int getIdx(const void* __restrict__ p, long long i) {
    if (g_is64) return (int)((const long long*)p)[i];
    return ((const int*)p)[i];
}

__global__ void k_probe_zero(const void* __restrict__ ei) {
    int i = blockIdx.x * blockDim.x + threadIdx.x;
    if (i == 0) {
        const unsigned* w = (const unsigned*)ei;
        int all0 = 1;
        #pragma unroll
        for (int k = 0; k < 64; k++) all0 &= (w[2 * k + 1] == 0u);
        g_is64 = all0;
    }
    if (i < N_NODES) { g_deg[i] = 0; g_cnt[i] = 0; }
}

__global__ void k_deg(const void* __restrict__ ei) {
    int e = blockIdx.x * blockDim.x + threadIdx.x;
    if (e >= N_EDGESC) return;
    atomicAdd(&g_deg[getIdx(ei, (long long)N_EDGESC + e)], 1);
}

// ---- 3-kernel parallel exclusive scan of (deg+1) --------------------------
__global__ void k_scanA() {
    __shared__ int sw[32];
    int tid = threadIdx.x, lane = tid & 31, wid = tid >> 5;
    int idx = blockIdx.x * 1024 + tid;
    int orig = (idx < N_NODES) ? (g_deg[idx] + 1) : 0;
    int v = orig;
    #pragma unroll
    for (int off = 1; off < 32; off <<= 1) {
        int t = __shfl_up_sync(0xffffffffu, v, off);
        if (lane >= off) v += t;
    }
    if (lane == 31) sw[wid] = v;
    __syncthreads();
    if (wid == 0) {
        int w = sw[lane];
        #pragma unroll
        for (int off = 1; off < 32; off <<= 1) {
            int t = __shfl_up_sync(0xffffffffu, w, off);
            if (lane >= off) w += t;
        }
        sw[lane] = w;
    }
    __syncthreads();
    int incl = v + (wid ? sw[wid - 1] : 0);
    if (idx < N_NODES) g_rowptr[idx] = incl - orig;   // block-local exclusive
    if (tid == 1023) g_bsum[blockIdx.x] = incl;
}

__global__ void k_scanB() {       // one warp: exclusive scan of block sums
    int lane = threadIdx.x;
    int v0 = (lane < SCAN_NB) ? g_bsum[lane] : 0;
    int i0 = v0;
    #pragma unroll
    for (int off = 1; off < 32; off <<= 1) {
        int t = __shfl_up_sync(0xffffffffu, i0, off);
        if (lane >= off) i0 += t;
    }
    int tot0 = __shfl_sync(0xffffffffu, i0, 31);
    if (lane < SCAN_NB) g_boff[lane] = i0 - v0;
    int j = 32 + lane;
    int v1 = (j < SCAN_NB) ? g_bsum[j] : 0;
    int i1 = v1;
    #pragma unroll
    for (int off = 1; off < 32; off <<= 1) {
        int t = __shfl_up_sync(0xffffffffu, i1, off);
        if (lane >= off) i1 += t;
    }
    if (j < SCAN_NB) g_boff[j] = tot0 + i1 - v1;
}

__global__ void k_scanC() {       // add offsets + self-loop slots
    int idx = blockIdx.x * blockDim.x + threadIdx.x;
    if (idx == 0) g_rowptr[N_NODES] = ET;
    if (idx >= N_NODES) return;
    int p = g_rowptr[idx] + g_boff[idx >> 10];
    g_rowptr[idx] = p;
    g_srcs[p] = idx;
    g_dsts[p] = idx;
}

// counting-sort scatter of real edges by dst; records inverse permutation
__global__ void k_scatter(const void* __restrict__ ei) {
    int e = blockIdx.x * blockDim.x + threadIdx.x;
    if (e >= N_EDGESC) return;
    int src = getIdx(ei, e);
    int dst = getIdx(ei, (long long)N_EDGESC + e);
    int p = g_rowptr[dst] + 1 + atomicAdd(&g_cnt[dst], 1);
    g_srcs[p] = src;
    g_dsts[p] = dst;
    g_slot[e] = p;
}

// permute attrs into CSR order: sequential reads x4 (MLP=4), scattered writes
__global__ void __launch_bounds__(256) k_permute(const float* __restrict__ ea) {
    int wid = (blockIdx.x * blockDim.x + threadIdx.x) >> 5;
    int nw  = (gridDim.x * blockDim.x) >> 5;
    int lane = threadIdx.x & 31;
    for (int e = wid * 4; e < N_EDGESC; e += nw * 4) {
        float v0 = ea[(long long)(e + 0) * FE + lane];
        float v1 = ea[(long long)(e + 1) * FE + lane];
        float v2 = ea[(long long)(e + 2) * FE + lane];
        float v3 = ea[(long long)(e + 3) * FE + lane];
        int s0 = g_slot[e + 0], s1 = g_slot[e + 1];
        int s2 = g_slot[e + 2], s3 = g_slot[e + 3];
        g_eas[(long long)s0 * FE + lane] = v0;
        g_eas[(long long)s1 * FE + lane] = v1;
        g_eas[(long long)s2 * FE + lane] = v2;
        g_eas[(long long)s3 * FE + lane] = v3;
    }
}

// self-loop attr = mean of incoming attrs (contiguous reads, dual accumulators)
__global__ void __launch_bounds__(256) k_loopcsr() {
    int wid = (blockIdx.x * blockDim.x + threadIdx.x) >> 5;
    if (wid >= N_NODES) return;
    int lane = threadIdx.x & 31;
    int beg = g_rowptr[wid], end = g_rowptr[wid + 1];
    float acc0 = 0.f, acc1 = 0.f;
    int i = beg + 1;
    for (; i + 1 < end; i += 2) {
        acc0 += g_eas[(long long)i * FE + lane];
        acc1 += g_eas[(long long)(i + 1) * FE + lane];
    }
    if (i < end) acc0 += g_eas[(long long)i * FE + lane];
    float d = (float)(end - beg - 1);
    g_eas[(long long)beg * FE + lane] = (acc0 + acc1) / fmaxf(d, 1.f);
}

// ---------------- node GEMMs: xl = h@Wl + bl, xr = h@Wr + br ------------------
__global__ void __launch_bounds__(128) k_xlxr(
    const float* __restrict__ x_ext, int hin_sel,
    const float* __restrict__ Wl, const float* __restrict__ bl,
    const float* __restrict__ Wr, const float* __restrict__ br) {
    const float* h = (hin_sel == 0) ? x_ext : (hin_sel == 1 ? g_hA : g_hB);
    __shared__ float shT[F][34];
    int j = threadIdx.x;
    int r0 = blockIdx.x * 32;
    #pragma unroll
    for (int r = 0; r < 32; r++) {
        int row = r0 + r;
        shT[j][r] = (row < N_NODES) ? h[(long long)row * F + j] : 0.f;
    }
    __syncthreads();
    u64 aL[16], aR[16];
    {
        u64 bl2 = pack2(bl[j], bl[j]);
        u64 br2 = pack2(br[j], br[j]);
        #pragma unroll
        for (int rp = 0; rp < 16; rp++) { aL[rp] = bl2; aR[rp] = br2; }
    }
    #pragma unroll 2
    for (int k = 0; k < F; k++) {
        float wl = Wl[k * F + j];
        float wr = Wr[k * F + j];
        u64 wl2 = pack2(wl, wl);
        u64 wr2 = pack2(wr, wr);
        #pragma unroll
        for (int rp = 0; rp < 16; rp++) {
            u64 hv2 = *(const u64*)&shT[k][2 * rp];
            aL[rp] = ffma2(hv2, wl2, aL[rp]);
            aR[rp] = ffma2(hv2, wr2, aR[rp]);
        }
    }
    #pragma unroll
    for (int rp = 0; rp < 16; rp++) {
        float2 l = unpack2(aL[rp]);
        float2 r = unpack2(aR[rp]);
        int row = r0 + 2 * rp;
        if (row < N_NODES)     { g_xl[(long long)row * F + j] = l.x; g_xr[(long long)row * F + j] = r.x; }
        if (row + 1 < N_NODES) { g_xl[(long long)(row + 1) * F + j] = l.y; g_xr[(long long)(row + 1) * F + j] = r.y; }
    }
}

// ---------------- per-edge attention score: warp-pair column split -----------
__global__ void __launch_bounds__(128, 4) k_score(
    const float* __restrict__ We, const float* __restrict__ att) {
    __shared__ float2 sa[2][32][32];    // duplicated attr pairs, 16KB
    __shared__ float  sp[4][32];        // per-warp partial scores
    int lane = threadIdx.x & 31;
    int wib  = threadIdx.x >> 5;        // 0..3
    int pair = wib >> 1;                // tile index within block
    int half = wib & 1;                 // column half
    int ntiles = (ET + 31) / 32;
    int tile = blockIdx.x * 2 + pair;
    long long base = (long long)tile * 32;
    int n = 0;
    if (tile < ntiles) n = (int)min((long long)32, (long long)ET - base);

    // cooperative attr staging: pair's warps do alternating rows
    for (int j = half; j < n; j += 2) {
        float a = g_eas[(base + j) * FE + lane];
        sa[pair][j][lane] = make_float2(a, a);
    }
    __syncthreads();

    float sc = 0.f;
    if (n > 0) {
        u64 w[FE];
        const float* wp = We + 64 * half + 2 * lane;
        #pragma unroll
        for (int k = 0; k < FE; k++) {
            float2 wv = *(const float2*)(wp + k * F);
            w[k] = pack2(wv.x, wv.y);
        }
        float2 at2 = *(const float2*)(att + 64 * half + 2 * lane);
        const float* xlb = g_xl + 64 * half + 2 * lane;
        const float* xrb = g_xr + 64 * half + 2 * lane;
        int src_l = (lane < n) ? g_srcs[base + lane] : 0;
        int dst_l = (lane < n) ? g_dsts[base + lane] : 0;

        float2 xlA, xrA, xlB, xrB;
        {
            int s = __shfl_sync(0xffffffffu, src_l, 0);
            int d = __shfl_sync(0xffffffffu, dst_l, 0);
            xlA = *(const float2*)(xlb + (long long)s * F);
            xrA = *(const float2*)(xrb + (long long)d * F);
        }
        xlB = xlA; xrB = xrA;
        if (n > 1) {
            int s = __shfl_sync(0xffffffffu, src_l, 1);
            int d = __shfl_sync(0xffffffffu, dst_l, 1);
            xlB = *(const float2*)(xlb + (long long)s * F);
            xrB = *(const float2*)(xrb + (long long)d * F);
        }

        int j = 0;
        while (j < n) {
            {   // edge j (slot A); prefetch j+2 into A
                float2 xl_c = xlA, xr_c = xrA;
                if (j + 2 < n) {
                    int s = __shfl_sync(0xffffffffu, src_l, j + 2);
                    int d = __shfl_sync(0xffffffffu, dst_l, j + 2);
                    xlA = *(const float2*)(xlb + (long long)s * F);
                    xrA = *(const float2*)(xrb + (long long)d * F);
                }
                u64 acc0 = pack2(xl_c.x + xr_c.x, xl_c.y + xr_c.y);
                u64 acc1 = pack2(0.f, 0.f);
                const float4* sprow = (const float4*)sa[pair][j];
                #pragma unroll
                for (int kk = 0; kk < FE / 2; kk++) {
                    float4 q = sprow[kk];              // uniform LDS.128
                    acc0 = ffma2(pack2(q.x, q.y), w[2 * kk], acc0);
                    acc1 = ffma2(pack2(q.z, q.w), w[2 * kk + 1], acc1);
                }
                float2 e0 = unpack2(acc0);
                float2 e1 = unpack2(acc1);
                float c0 = e0.x + e1.x, c1 = e0.y + e1.y;
                float t0 = c0 > 0.f ? c0 : SLOPE * c0;
                float t1 = c1 > 0.f ? c1 : SLOPE * c1;
                float p = t0 * at2.x + t1 * at2.y;
                #pragma unroll
                for (int off = 16; off; off >>= 1) p += __shfl_xor_sync(0xffffffffu, p, off);
                if (lane == j) sc = p;
            }
            j++;
            if (j >= n) break;
            {   // edge j (slot B); prefetch j+2 into B
                float2 xl_c = xlB, xr_c = xrB;
                if (j + 2 < n) {
                    int s = __shfl_sync(0xffffffffu, src_l, j + 2);
                    int d = __shfl_sync(0xffffffffu, dst_l, j + 2);
                    xlB = *(const float2*)(xlb + (long long)s * F);
                    xrB = *(const float2*)(xrb + (long long)d * F);
                }
                u64 acc0 = pack2(xl_c.x + xr_c.x, xl_c.y + xr_c.y);
                u64 acc1 = pack2(0.f, 0.f);
                const float4* sprow = (const float4*)sa[pair][j];
                #pragma unroll
                for (int kk = 0; kk < FE / 2; kk++) {
                    float4 q = sprow[kk];
                    acc0 = ffma2(pack2(q.x, q.y), w[2 * kk], acc0);
                    acc1 = ffma2(pack2(q.z, q.w), w[2 * kk + 1], acc1);
                }
                float2 e0 = unpack2(acc0);
                float2 e1 = unpack2(acc1);
                float c0 = e0.x + e1.x, c1 = e0.y + e1.y;
                float t0 = c0 > 0.f ? c0 : SLOPE * c0;
                float t1 = c1 > 0.f ? c1 : SLOPE * c1;
                float p = t0 * at2.x + t1 * at2.y;
                #pragma unroll
                for (int off = 16; off; off >>= 1) p += __shfl_xor_sync(0xffffffffu, p, off);
                if (lane == j) sc = p;
            }
            j++;
        }
    }
    sp[wib][lane] = sc;
    __syncthreads();
    if (half == 0 && lane < n)
        g_score[base + lane] = sp[wib][lane] + sp[wib + 1][lane];
}

// ---------------- softmax aggregation, two-pass (warp per node) --------------
__global__ void __launch_bounds__(256) k_agg(
    const float* __restrict__ bias, int hout_sel) {
    int wid = (blockIdx.x * blockDim.x + threadIdx.x) >> 5;
    if (wid >= N_NODES) return;
    float* hout = (hout_sel == 1) ? g_hB : g_hA;
    int lane = threadIdx.x & 31;
    int beg = g_rowptr[wid], end = g_rowptr[wid + 1];

    float m = -3.0e38f;
    for (int t = beg + lane; t < end; t += 32) m = fmaxf(m, g_score[t]);
    #pragma unroll
    for (int off = 16; off; off >>= 1) m = fmaxf(m, __shfl_xor_sync(0xffffffffu, m, off));
    float den = 0.f;
    for (int t = beg + lane; t < end; t += 32) den += __expf(g_score[t] - m);
    #pragma unroll
    for (int off = 16; off; off >>= 1) den += __shfl_xor_sync(0xffffffffu, den, off);
    float inv = 1.f / den;

    float4 a0 = make_float4(0.f, 0.f, 0.f, 0.f), a1 = a0, a2 = a0, a3 = a0;
    for (int t = beg; t < end; t += 32) {
        int idx = t + lane;
        bool ok = idx < end;
        float pe = ok ? __expf(g_score[idx] - m) : 0.f;
        int   sr = ok ? g_srcs[idx] : 0;
        int cnt = min(32, end - t);
        int j = 0;
        for (; j + 4 <= cnt; j += 4) {
            float p0 = __shfl_sync(0xffffffffu, pe, j);
            float p1 = __shfl_sync(0xffffffffu, pe, j + 1);
            float p2 = __shfl_sync(0xffffffffu, pe, j + 2);
            float p3 = __shfl_sync(0xffffffffu, pe, j + 3);
            int s0 = __shfl_sync(0xffffffffu, sr, j);
            int s1 = __shfl_sync(0xffffffffu, sr, j + 1);
            int s2 = __shfl_sync(0xffffffffu, sr, j + 2);
            int s3 = __shfl_sync(0xffffffffu, sr, j + 3);
            float4 x0 = *(const float4*)(g_xl + (long long)s0 * F + 4 * lane);
            float4 x1 = *(const float4*)(g_xl + (long long)s1 * F + 4 * lane);
            float4 x2 = *(const float4*)(g_xl + (long long)s2 * F + 4 * lane);
            float4 x3 = *(const float4*)(g_xl + (long long)s3 * F + 4 * lane);
            a0.x += p0 * x0.x; a0.y += p0 * x0.y; a0.z += p0 * x0.z; a0.w += p0 * x0.w;
            a1.x += p1 * x1.x; a1.y += p1 * x1.y; a1.z += p1 * x1.z; a1.w += p1 * x1.w;
            a2.x += p2 * x2.x; a2.y += p2 * x2.y; a2.z += p2 * x2.z; a2.w += p2 * x2.w;
            a3.x += p3 * x3.x; a3.y += p3 * x3.y; a3.z += p3 * x3.z; a3.w += p3 * x3.w;
        }
        for (; j < cnt; j++) {
            float pj = __shfl_sync(0xffffffffu, pe, j);
            int   sj = __shfl_sync(0xffffffffu, sr, j);
            float4 xj = *(const float4*)(g_xl + (long long)sj * F + 4 * lane);
            a0.x += pj * xj.x; a0.y += pj * xj.y; a0.z += pj * xj.z; a0.w += pj * xj.w;
        }
    }
    float4 bi = *(const float4*)(bias + 4 * lane);
    float4 o;
    o.x = fmaxf((a0.x + a1.x + a2.x + a3.x) * inv + bi.x, 0.f);
    o.y = fmaxf((a0.y + a1.y + a2.y + a3.y) * inv + bi.y, 0.f);
    o.z = fmaxf((a0.z + a1.z + a2.z + a3.z) * inv + bi.z, 0.f);
    o.w = fmaxf((a0.w + a1.w + a2.w + a3.w) * inv + bi.w, 0.f);
    *(float4*)(hout + (long long)wid * F + 4 * lane) = o;
}

// ---------------- pool + classifier ----------------------------------------
__global__ void k_gptr(const void* __restrict__ batch) {
    int g = blockIdx.x * blockDim.x + threadIdx.x;
    if (g > NG) return;
    int lo = 0, hi = N_NODES;
    while (lo < hi) {
        int mid = (lo + hi) >> 1;
        if (getIdx(batch, mid) < g) lo = mid + 1; else hi = mid;
    }
    g_gptr[g] = lo;
}

__global__ void __launch_bounds__(128) k_poolg() {
    int g = blockIdx.x;
    int j = threadIdx.x;
    int b = g_gptr[g], e = g_gptr[g + 1];
    float acc = 0.f;
    for (int v = b; v < e; v++) acc += g_hA[(long long)v * F + j];
    float inv = 1.f / fmaxf((float)(e - b), 1.f);
    g_pool[g * F + j] = acc * inv;
}

__global__ void k_final(const float* __restrict__ lw, const float* __restrict__ lb,
                        float* __restrict__ out) {
    int t = blockIdx.x * blockDim.x + threadIdx.x;
    if (t >= NG * NC) return;
    int g = t / NC, cls = t % NC;
    float acc = lb[cls];
    #pragma unroll 8
    for (int c = 0; c < F; c++)
        acc += g_pool[g * F + c] * lw[c * NC + cls];
    out[t] = acc;
}

// ---------------- host -------------------------------------------------------
extern "C" void kernel_launch(void* const* d_in, const int* in_sizes, int n_in,
                              void* d_out, int out_size) {
    (void)in_sizes; (void)n_in; (void)out_size;
    const float* x     = (const float*)d_in[0];
    const void*  ei    = d_in[1];
    const void*  batch = d_in[2];
    // d_in[3] = dropout (identity in eval)
    const float* ea   = (const float*)d_in[4];
    const float* Wl   = (const float*)d_in[5];
    const float* bl   = (const float*)d_in[6];
    const float* Wr   = (const float*)d_in[7];
    const float* br   = (const float*)d_in[8];
    const float* We   = (const float*)d_in[9];
    const float* att  = (const float*)d_in[10];
    const float* bias = (const float*)d_in[11];
    const float* lw   = (const float*)d_in[12];
    const float* lb   = (const float*)d_in[13];
    float* out = (float*)d_out;

    k_probe_zero<<<(N_NODES + 255) / 256, 256>>>(ei);
    k_deg<<<(N_EDGESC + 255) / 256, 256>>>(ei);
    k_scanA<<<SCAN_NB, 1024>>>();
    k_scanB<<<1, 32>>>();
    k_scanC<<<(N_NODES + 255) / 256, 256>>>();
    k_scatter<<<(N_EDGESC + 255) / 256, 256>>>(ei);
    k_permute<<<2048, 256>>>(ea);
    k_loopcsr<<<(N_NODES * 32 + 255) / 256, 256>>>();

    int ntiles = (ET + 31) / 32;
    int nblocks = (ntiles + 1) / 2;       // 2 tiles (4 warps) per block
    for (int l = 0; l < 3; l++) {
        int hin  = l;                 // 0: x, 1: hA, 2: hB
        int hout = (l == 1) ? 1 : 0;  // layer0 -> hA, layer1 -> hB, layer2 -> hA
        k_xlxr<<<(N_NODES + 31) / 32, 128>>>(x, hin,
                                             Wl + (size_t)l * F * F, bl + (size_t)l * F,
                                             Wr + (size_t)l * F * F, br + (size_t)l * F);
        // MEASUREMENT: k_score launched twice (idempotent). dur - 2395us = 3*T_score.
        k_score<<<nblocks, 128>>>(We + (size_t)l * FE * F, att + (size_t)l * F);
        k_score<<<nblocks, 128>>>(We + (size_t)l * FE * F, att + (size_t)l * F);
        k_agg<<<(N_NODES * 32 + 255) / 256, 256>>>(bias + (size_t)l * F, hout);
    }

    k_gptr<<<3, 256>>>(batch);
    k_poolg<<<NG, 128>>>();
    k_final<<<(NG * NC + 127) / 128, 128>>>(lw, lb, out);
}

// round 15
// speedup vs baseline: 1.5613x; 1.5613x over previous
#include <cuda_runtime.h>
#include <cuda_bf16.h>

#define N_NODES  50000
#define N_EDGESC 1600000
#define ET       1650000            // edges + self loops
#define F        128
#define FE       32
#define NG       512
#define NC       10
#define SLOPE    0.2f
#define SCAN_NB  ((N_NODES + 1023) / 1024)   // 49

typedef unsigned long long u64;

// ---------------- f32x2 helpers (Blackwell packed fp32) ----------------------
__device__ __forceinline__ u64 pack2(float x, float y) {
    u64 r; asm("mov.b64 %0, {%1, %2};" : "=l"(r) : "f"(x), "f"(y)); return r;
}
__device__ __forceinline__ float2 unpack2(u64 v) {
    float2 f; asm("mov.b64 {%0, %1}, %2;" : "=f"(f.x), "=f"(f.y) : "l"(v)); return f;
}
__device__ __forceinline__ u64 ffma2(u64 a, u64 b, u64 c) {
    u64 d; asm("fma.rn.f32x2 %0, %1, %2, %3;" : "=l"(d) : "l"(a), "l"(b), "l"(c)); return d;
}

// ---------------- scratch (device globals: allocation-free rule) -------------
__device__ float g_eas[(size_t)ET * FE];   // edge attrs in CSR slot order (211MB)
__device__ float g_score[ET];
__device__ float g_xl[(size_t)N_NODES * F];
__device__ float g_xr[(size_t)N_NODES * F];
__device__ float g_hA[(size_t)N_NODES * F];
__device__ float g_hB[(size_t)N_NODES * F];
__device__ int   g_deg[N_NODES];
__device__ int   g_rowptr[N_NODES + 1];
__device__ int   g_cnt[N_NODES];
__device__ int   g_srcs[ET];
__device__ int   g_dsts[ET];
__device__ int   g_slot[N_EDGESC];
__device__ int   g_bsum[64];
__device__ int   g_boff[64];
__device__ int   g_gptr[NG + 1];
__device__ float g_pool[NG * F];
__device__ int   g_is64;

// ---------------- index dtype handling --------------------------------------
__device__ __forceinline__ int getIdx(const void* __restrict__ p, long long i) {
    if (g_is64) return (int)((const long long*)p)[i];
    return ((const int*)p)[i];
}

__global__ void k_probe_zero(const void* __restrict__ ei) {
    int i = blockIdx.x * blockDim.x + threadIdx.x;
    if (i == 0) {
        const unsigned* w = (const unsigned*)ei;
        int all0 = 1;
        #pragma unroll
        for (int k = 0; k < 64; k++) all0 &= (w[2 * k + 1] == 0u);
        g_is64 = all0;
    }
    if (i < N_NODES) { g_deg[i] = 0; g_cnt[i] = 0; }
}

__global__ void k_deg(const void* __restrict__ ei) {
    int e = blockIdx.x * blockDim.x + threadIdx.x;
    if (e >= N_EDGESC) return;
    atomicAdd(&g_deg[getIdx(ei, (long long)N_EDGESC + e)], 1);
}

// ---- 3-kernel parallel exclusive scan of (deg+1) --------------------------
__global__ void k_scanA() {
    __shared__ int sw[32];
    int tid = threadIdx.x, lane = tid & 31, wid = tid >> 5;
    int idx = blockIdx.x * 1024 + tid;
    int orig = (idx < N_NODES) ? (g_deg[idx] + 1) : 0;
    int v = orig;
    #pragma unroll
    for (int off = 1; off < 32; off <<= 1) {
        int t = __shfl_up_sync(0xffffffffu, v, off);
        if (lane >= off) v += t;
    }
    if (lane == 31) sw[wid] = v;
    __syncthreads();
    if (wid == 0) {
        int w = sw[lane];
        #pragma unroll
        for (int off = 1; off < 32; off <<= 1) {
            int t = __shfl_up_sync(0xffffffffu, w, off);
            if (lane >= off) w += t;
        }
        sw[lane] = w;
    }
    __syncthreads();
    int incl = v + (wid ? sw[wid - 1] : 0);
    if (idx < N_NODES) g_rowptr[idx] = incl - orig;   // block-local exclusive
    if (tid == 1023) g_bsum[blockIdx.x] = incl;
}

__global__ void k_scanB() {       // one warp: exclusive scan of block sums
    int lane = threadIdx.x;
    int v0 = (lane < SCAN_NB) ? g_bsum[lane] : 0;
    int i0 = v0;
    #pragma unroll
    for (int off = 1; off < 32; off <<= 1) {
        int t = __shfl_up_sync(0xffffffffu, i0, off);
        if (lane >= off) i0 += t;
    }
    int tot0 = __shfl_sync(0xffffffffu, i0, 31);
    if (lane < SCAN_NB) g_boff[lane] = i0 - v0;
    int j = 32 + lane;
    int v1 = (j < SCAN_NB) ? g_bsum[j] : 0;
    int i1 = v1;
    #pragma unroll
    for (int off = 1; off < 32; off <<= 1) {
        int t = __shfl_up_sync(0xffffffffu, i1, off);
        if (lane >= off) i1 += t;
    }
    if (j < SCAN_NB) g_boff[j] = tot0 + i1 - v1;
}

__global__ void k_scanC() {       // add offsets + self-loop slots
    int idx = blockIdx.x * blockDim.x + threadIdx.x;
    if (idx == 0) g_rowptr[N_NODES] = ET;
    if (idx >= N_NODES) return;
    int p = g_rowptr[idx] + g_boff[idx >> 10];
    g_rowptr[idx] = p;
    g_srcs[p] = idx;
    g_dsts[p] = idx;
}

// counting-sort scatter of real edges by dst; records inverse permutation
__global__ void k_scatter(const void* __restrict__ ei) {
    int e = blockIdx.x * blockDim.x + threadIdx.x;
    if (e >= N_EDGESC) return;
    int src = getIdx(ei, e);
    int dst = getIdx(ei, (long long)N_EDGESC + e);
    int p = g_rowptr[dst] + 1 + atomicAdd(&g_cnt[dst], 1);
    g_srcs[p] = src;
    g_dsts[p] = dst;
    g_slot[e] = p;
}

// permute attrs into CSR order: sequential reads x4 (MLP=4), scattered writes
__global__ void __launch_bounds__(256) k_permute(const float* __restrict__ ea) {
    int wid = (blockIdx.x * blockDim.x + threadIdx.x) >> 5;
    int nw  = (gridDim.x * blockDim.x) >> 5;
    int lane = threadIdx.x & 31;
    for (int e = wid * 4; e < N_EDGESC; e += nw * 4) {
        float v0 = ea[(long long)(e + 0) * FE + lane];
        float v1 = ea[(long long)(e + 1) * FE + lane];
        float v2 = ea[(long long)(e + 2) * FE + lane];
        float v3 = ea[(long long)(e + 3) * FE + lane];
        int s0 = g_slot[e + 0], s1 = g_slot[e + 1];
        int s2 = g_slot[e + 2], s3 = g_slot[e + 3];
        g_eas[(long long)s0 * FE + lane] = v0;
        g_eas[(long long)s1 * FE + lane] = v1;
        g_eas[(long long)s2 * FE + lane] = v2;
        g_eas[(long long)s3 * FE + lane] = v3;
    }
}

// self-loop attr = mean of incoming attrs (contiguous reads, dual accumulators)
__global__ void __launch_bounds__(256) k_loopcsr() {
    int wid = (blockIdx.x * blockDim.x + threadIdx.x) >> 5;
    if (wid >= N_NODES) return;
    int lane = threadIdx.x & 31;
    int beg = g_rowptr[wid], end = g_rowptr[wid + 1];
    float acc0 = 0.f, acc1 = 0.f;
    int i = beg + 1;
    for (; i + 1 < end; i += 2) {
        acc0 += g_eas[(long long)i * FE + lane];
        acc1 += g_eas[(long long)(i + 1) * FE + lane];
    }
    if (i < end) acc0 += g_eas[(long long)i * FE + lane];
    float d = (float)(end - beg - 1);
    g_eas[(long long)beg * FE + lane] = (acc0 + acc1) / fmaxf(d, 1.f);
}

// ---------------- node GEMMs: xl = h@Wl + bl, xr = h@Wr + br ------------------
__global__ void __launch_bounds__(128) k_xlxr(
    const float* __restrict__ x_ext, int hin_sel,
    const float* __restrict__ Wl, const float* __restrict__ bl,
    const float* __restrict__ Wr, const float* __restrict__ br) {
    const float* h = (hin_sel == 0) ? x_ext : (hin_sel == 1 ? g_hA : g_hB);
    __shared__ float shT[F][34];
    int j = threadIdx.x;
    int r0 = blockIdx.x * 32;
    #pragma unroll
    for (int r = 0; r < 32; r++) {
        int row = r0 + r;
        shT[j][r] = (row < N_NODES) ? h[(long long)row * F + j] : 0.f;
    }
    __syncthreads();
    u64 aL[16], aR[16];
    {
        u64 bl2 = pack2(bl[j], bl[j]);
        u64 br2 = pack2(br[j], br[j]);
        #pragma unroll
        for (int rp = 0; rp < 16; rp++) { aL[rp] = bl2; aR[rp] = br2; }
    }
    #pragma unroll 2
    for (int k = 0; k < F; k++) {
        float wl = Wl[k * F + j];
        float wr = Wr[k * F + j];
        u64 wl2 = pack2(wl, wl);
        u64 wr2 = pack2(wr, wr);
        #pragma unroll
        for (int rp = 0; rp < 16; rp++) {
            u64 hv2 = *(const u64*)&shT[k][2 * rp];
            aL[rp] = ffma2(hv2, wl2, aL[rp]);
            aR[rp] = ffma2(hv2, wr2, aR[rp]);
        }
    }
    #pragma unroll
    for (int rp = 0; rp < 16; rp++) {
        float2 l = unpack2(aL[rp]);
        float2 r = unpack2(aR[rp]);
        int row = r0 + 2 * rp;
        if (row < N_NODES)     { g_xl[(long long)row * F + j] = l.x; g_xr[(long long)row * F + j] = r.x; }
        if (row + 1 < N_NODES) { g_xl[(long long)(row + 1) * F + j] = l.y; g_xr[(long long)(row + 1) * F + j] = r.y; }
    }
}

// ---------------- per-edge attention score: burst-gather + smem compute ------
// Warp-pair per 32-edge tile, column-split (64 cols/warp). Gathers are issued
// in 16-edge bursts (32 independent float2 loads, MLP~32) into smem; the GEMV
// loop then runs entirely from smem with zero global-latency exposure.
#define SC_CHUNK 16
__global__ void __launch_bounds__(128, 4) k_score(
    const float* __restrict__ We, const float* __restrict__ att) {
    __shared__ float2 sa[2][32][32];            // duplicated attr pairs, 16KB
    __shared__ float2 sxlr[4][SC_CHUNK][32];    // xl[src]+xr[dst] slices, 16KB
    __shared__ float  sp[4][32];                // per-warp partial scores
    int lane = threadIdx.x & 31;
    int wib  = threadIdx.x >> 5;        // 0..3
    int pair = wib >> 1;                // tile index within block
    int half = wib & 1;                 // column half
    int ntiles = (ET + 31) / 32;
    int tile = blockIdx.x * 2 + pair;
    long long base = (long long)tile * 32;
    int n = 0;
    if (tile < ntiles) n = (int)min((long long)32, (long long)ET - base);

    // cooperative attr staging: pair's warps do alternating rows
    for (int j = half; j < n; j += 2) {
        float a = g_eas[(base + j) * FE + lane];
        sa[pair][j][lane] = make_float2(a, a);
    }

    u64 w[FE];
    {
        const float* wp = We + 64 * half + 2 * lane;
        #pragma unroll
        for (int k = 0; k < FE; k++) {
            float2 wv = *(const float2*)(wp + k * F);
            w[k] = pack2(wv.x, wv.y);
        }
    }
    float2 at2 = *(const float2*)(att + 64 * half + 2 * lane);
    const float* xlb = g_xl + 64 * half + 2 * lane;
    const float* xrb = g_xr + 64 * half + 2 * lane;
    int src_l = (lane < n) ? g_srcs[base + lane] : 0;
    int dst_l = (lane < n) ? g_dsts[base + lane] : 0;
    __syncthreads();    // attrs staged

    float sc = 0.f;
    for (int c0 = 0; c0 < n; c0 += SC_CHUNK) {
        int cn = min(SC_CHUNK, n - c0);
        // burst: 2*cn independent coalesced float2 gathers
        #pragma unroll 4
        for (int j = 0; j < cn; j++) {
            int s = __shfl_sync(0xffffffffu, src_l, c0 + j);
            int d = __shfl_sync(0xffffffffu, dst_l, c0 + j);
            float2 xl2 = *(const float2*)(xlb + (long long)s * F);
            float2 xr2 = *(const float2*)(xrb + (long long)d * F);
            sxlr[wib][j][lane] = make_float2(xl2.x + xr2.x, xl2.y + xr2.y);
        }
        __syncwarp();
        // compute: all operands in smem
        for (int j = 0; j < cn; j++) {
            float2 u = sxlr[wib][j][lane];
            u64 acc0 = pack2(u.x, u.y);
            u64 acc1 = pack2(0.f, 0.f);
            const float4* sprow = (const float4*)sa[pair][c0 + j];
            #pragma unroll
            for (int kk = 0; kk < FE / 2; kk++) {
                float4 q = sprow[kk];              // uniform LDS.128 broadcast
                acc0 = ffma2(pack2(q.x, q.y), w[2 * kk], acc0);
                acc1 = ffma2(pack2(q.z, q.w), w[2 * kk + 1], acc1);
            }
            float2 e0 = unpack2(acc0);
            float2 e1 = unpack2(acc1);
            float c0v = e0.x + e1.x, c1v = e0.y + e1.y;
            float t0 = c0v > 0.f ? c0v : SLOPE * c0v;
            float t1 = c1v > 0.f ? c1v : SLOPE * c1v;
            float p = t0 * at2.x + t1 * at2.y;
            #pragma unroll
            for (int off = 16; off; off >>= 1) p += __shfl_xor_sync(0xffffffffu, p, off);
            if (lane == c0 + j) sc = p;
        }
        __syncwarp();   // before next burst overwrites sxlr
    }
    sp[wib][lane] = sc;
    __syncthreads();
    if (half == 0 && lane < n)
        g_score[base + lane] = sp[wib][lane] + sp[wib + 1][lane];
}

// ---------------- softmax aggregation, two-pass (warp per node) --------------
__global__ void __launch_bounds__(256) k_agg(
    const float* __restrict__ bias, int hout_sel) {
    int wid = (blockIdx.x * blockDim.x + threadIdx.x) >> 5;
    if (wid >= N_NODES) return;
    float* hout = (hout_sel == 1) ? g_hB : g_hA;
    int lane = threadIdx.x & 31;
    int beg = g_rowptr[wid], end = g_rowptr[wid + 1];

    float m = -3.0e38f;
    for (int t = beg + lane; t < end; t += 32) m = fmaxf(m, g_score[t]);
    #pragma unroll
    for (int off = 16; off; off >>= 1) m = fmaxf(m, __shfl_xor_sync(0xffffffffu, m, off));
    float den = 0.f;
    for (int t = beg + lane; t < end; t += 32) den += __expf(g_score[t] - m);
    #pragma unroll
    for (int off = 16; off; off >>= 1) den += __shfl_xor_sync(0xffffffffu, den, off);
    float inv = 1.f / den;

    float4 a0 = make_float4(0.f, 0.f, 0.f, 0.f), a1 = a0, a2 = a0, a3 = a0;
    for (int t = beg; t < end; t += 32) {
        int idx = t + lane;
        bool ok = idx < end;
        float pe = ok ? __expf(g_score[idx] - m) : 0.f;
        int   sr = ok ? g_srcs[idx] : 0;
        int cnt = min(32, end - t);
        int j = 0;
        for (; j + 4 <= cnt; j += 4) {
            float p0 = __shfl_sync(0xffffffffu, pe, j);
            float p1 = __shfl_sync(0xffffffffu, pe, j + 1);
            float p2 = __shfl_sync(0xffffffffu, pe, j + 2);
            float p3 = __shfl_sync(0xffffffffu, pe, j + 3);
            int s0 = __shfl_sync(0xffffffffu, sr, j);
            int s1 = __shfl_sync(0xffffffffu, sr, j + 1);
            int s2 = __shfl_sync(0xffffffffu, sr, j + 2);
            int s3 = __shfl_sync(0xffffffffu, sr, j + 3);
            float4 x0 = *(const float4*)(g_xl + (long long)s0 * F + 4 * lane);
            float4 x1 = *(const float4*)(g_xl + (long long)s1 * F + 4 * lane);
            float4 x2 = *(const float4*)(g_xl + (long long)s2 * F + 4 * lane);
            float4 x3 = *(const float4*)(g_xl + (long long)s3 * F + 4 * lane);
            a0.x += p0 * x0.x; a0.y += p0 * x0.y; a0.z += p0 * x0.z; a0.w += p0 * x0.w;
            a1.x += p1 * x1.x; a1.y += p1 * x1.y; a1.z += p1 * x1.z; a1.w += p1 * x1.w;
            a2.x += p2 * x2.x; a2.y += p2 * x2.y; a2.z += p2 * x2.z; a2.w += p2 * x2.w;
            a3.x += p3 * x3.x; a3.y += p3 * x3.y; a3.z += p3 * x3.z; a3.w += p3 * x3.w;
        }
        for (; j < cnt; j++) {
            float pj = __shfl_sync(0xffffffffu, pe, j);
            int   sj = __shfl_sync(0xffffffffu, sr, j);
            float4 xj = *(const float4*)(g_xl + (long long)sj * F + 4 * lane);
            a0.x += pj * xj.x; a0.y += pj * xj.y; a0.z += pj * xj.z; a0.w += pj * xj.w;
        }
    }
    float4 bi = *(const float4*)(bias + 4 * lane);
    float4 o;
    o.x = fmaxf((a0.x + a1.x + a2.x + a3.x) * inv + bi.x, 0.f);
    o.y = fmaxf((a0.y + a1.y + a2.y + a3.y) * inv + bi.y, 0.f);
    o.z = fmaxf((a0.z + a1.z + a2.z + a3.z) * inv + bi.z, 0.f);
    o.w = fmaxf((a0.w + a1.w + a2.w + a3.w) * inv + bi.w, 0.f);
    *(float4*)(hout + (long long)wid * F + 4 * lane) = o;
}

// ---------------- pool + classifier ----------------------------------------
__global__ void k_gptr(const void* __restrict__ batch) {
    int g = blockIdx.x * blockDim.x + threadIdx.x;
    if (g > NG) return;
    int lo = 0, hi = N_NODES;
    while (lo < hi) {
        int mid = (lo + hi) >> 1;
        if (getIdx(batch, mid) < g) lo = mid + 1; else hi = mid;
    }
    g_gptr[g] = lo;
}

__global__ void __launch_bounds__(128) k_poolg() {
    int g = blockIdx.x;
    int j = threadIdx.x;
    int b = g_gptr[g], e = g_gptr[g + 1];
    float acc = 0.f;
    for (int v = b; v < e; v++) acc += g_hA[(long long)v * F + j];
    float inv = 1.f / fmaxf((float)(e - b), 1.f);
    g_pool[g * F + j] = acc * inv;
}

__global__ void k_final(const float* __restrict__ lw, const float* __restrict__ lb,
                        float* __restrict__ out) {
    int t = blockIdx.x * blockDim.x + threadIdx.x;
    if (t >= NG * NC) return;
    int g = t / NC, cls = t % NC;
    float acc = lb[cls];
    #pragma unroll 8
    for (int c = 0; c < F; c++)
        acc += g_pool[g * F + c] * lw[c * NC + cls];
    out[t] = acc;
}

// ---------------- host -------------------------------------------------------
extern "C" void kernel_launch(void* const* d_in, const int* in_sizes, int n_in,
                              void* d_out, int out_size) {
    (void)in_sizes; (void)n_in; (void)out_size;
    const float* x     = (const float*)d_in[0];
    const void*  ei    = d_in[1];
    const void*  batch = d_in[2];
    // d_in[3] = dropout (identity in eval)
    const float* ea   = (const float*)d_in[4];
    const float* Wl   = (const float*)d_in[5];
    const float* bl   = (const float*)d_in[6];
    const float* Wr   = (const float*)d_in[7];
    const float* br   = (const float*)d_in[8];
    const float* We   = (const float*)d_in[9];
    const float* att  = (const float*)d_in[10];
    const float* bias = (const float*)d_in[11];
    const float* lw   = (const float*)d_in[12];
    const float* lb   = (const float*)d_in[13];
    float* out = (float*)d_out;

    k_probe_zero<<<(N_NODES + 255) / 256, 256>>>(ei);
    k_deg<<<(N_EDGESC + 255) / 256, 256>>>(ei);
    k_scanA<<<SCAN_NB, 1024>>>();
    k_scanB<<<1, 32>>>();
    k_scanC<<<(N_NODES + 255) / 256, 256>>>();
    k_scatter<<<(N_EDGESC + 255) / 256, 256>>>(ei);
    k_permute<<<2048, 256>>>(ea);
    k_loopcsr<<<(N_NODES * 32 + 255) / 256, 256>>>();

    int ntiles = (ET + 31) / 32;
    int nblocks = (ntiles + 1) / 2;       // 2 tiles (4 warps) per block
    for (int l = 0; l < 3; l++) {
        int hin  = l;                 // 0: x, 1: hA, 2: hB
        int hout = (l == 1) ? 1 : 0;  // layer0 -> hA, layer1 -> hB, layer2 -> hA
        k_xlxr<<<(N_NODES + 31) / 32, 128>>>(x, hin,
                                             Wl + (size_t)l * F * F, bl + (size_t)l * F,
                                             Wr + (size_t)l * F * F, br + (size_t)l * F);
        k_score<<<nblocks, 128>>>(We + (size_t)l * FE * F, att + (size_t)l * F);
        k_agg<<<(N_NODES * 32 + 255) / 256, 256>>>(bias + (size_t)l * F, hout);
    }

    k_gptr<<<3, 256>>>(batch);
    k_poolg<<<NG, 128>>>();
    k_final<<<(NG * NC + 127) / 128, 128>>>(lw, lb, out);
}

// round 16
// speedup vs baseline: 1.8836x; 1.2064x over previous
#include <cuda_runtime.h>
#include <cuda_bf16.h>

#define N_NODES  50000
#define N_EDGESC 1600000
#define ET       1650000            // edges + self loops
#define F        128
#define FE       32
#define NG       512
#define NC       10
#define SLOPE    0.2f
#define SCAN_NB  ((N_NODES + 1023) / 1024)   // 49

typedef unsigned long long u64;

// ---------------- f32x2 helpers (Blackwell packed fp32) ----------------------
__device__ __forceinline__ u64 pack2(float x, float y) {
    u64 r; asm("mov.b64 %0, {%1, %2};" : "=l"(r) : "f"(x), "f"(y)); return r;
}
__device__ __forceinline__ float2 unpack2(u64 v) {
    float2 f; asm("mov.b64 {%0, %1}, %2;" : "=f"(f.x), "=f"(f.y) : "l"(v)); return f;
}
__device__ __forceinline__ u64 ffma2(u64 a, u64 b, u64 c) {
    u64 d; asm("fma.rn.f32x2 %0, %1, %2, %3;" : "=l"(d) : "l"(a), "l"(b), "l"(c)); return d;
}

// ---------------- scratch (device globals: allocation-free rule) -------------
__device__ float g_eas[(size_t)ET * FE];   // edge attrs in CSR slot order (211MB)
__device__ float g_score[ET];
__device__ float g_xl[(size_t)N_NODES * F];
__device__ float g_xr[(size_t)N_NODES * F];
__device__ float g_hA[(size_t)N_NODES * F];
__device__ float g_hB[(size_t)N_NODES * F];
__device__ int   g_deg[N_NODES];
__device__ int   g_rowptr[N_NODES + 1];
__device__ int   g_cnt[N_NODES];
__device__ int   g_srcs[ET];
__device__ int   g_dsts[ET];
__device__ int   g_slot[N_EDGESC];
__device__ int   g_bsum[64];
__device__ int   g_boff[64];
__device__ int   g_gptr[NG + 1];
__device__ float g_pool[NG * F];
__device__ int   g_is64;

// ---------------- index dtype handling --------------------------------------
__device__ __forceinline__ int getIdx(const void* __restrict__ p, long long i) {
    if (g_is64) return (int)((const long long*)p)[i];
    return ((const int*)p)[i];
}

__global__ void k_probe_zero(const void* __restrict__ ei) {
    int i = blockIdx.x * blockDim.x + threadIdx.x;
    if (i == 0) {
        const unsigned* w = (const unsigned*)ei;
        int all0 = 1;
        #pragma unroll
        for (int k = 0; k < 64; k++) all0 &= (w[2 * k + 1] == 0u);
        g_is64 = all0;
    }
    if (i < N_NODES) { g_deg[i] = 0; g_cnt[i] = 0; }
}

__global__ void k_deg(const void* __restrict__ ei) {
    int e = blockIdx.x * blockDim.x + threadIdx.x;
    if (e >= N_EDGESC) return;
    atomicAdd(&g_deg[getIdx(ei, (long long)N_EDGESC + e)], 1);
}

// ---- 3-kernel parallel exclusive scan of (deg+1) --------------------------
__global__ void k_scanA() {
    __shared__ int sw[32];
    int tid = threadIdx.x, lane = tid & 31, wid = tid >> 5;
    int idx = blockIdx.x * 1024 + tid;
    int orig = (idx < N_NODES) ? (g_deg[idx] + 1) : 0;
    int v = orig;
    #pragma unroll
    for (int off = 1; off < 32; off <<= 1) {
        int t = __shfl_up_sync(0xffffffffu, v, off);
        if (lane >= off) v += t;
    }
    if (lane == 31) sw[wid] = v;
    __syncthreads();
    if (wid == 0) {
        int w = sw[lane];
        #pragma unroll
        for (int off = 1; off < 32; off <<= 1) {
            int t = __shfl_up_sync(0xffffffffu, w, off);
            if (lane >= off) w += t;
        }
        sw[lane] = w;
    }
    __syncthreads();
    int incl = v + (wid ? sw[wid - 1] : 0);
    if (idx < N_NODES) g_rowptr[idx] = incl - orig;   // block-local exclusive
    if (tid == 1023) g_bsum[blockIdx.x] = incl;
}

__global__ void k_scanB() {       // one warp: exclusive scan of block sums
    int lane = threadIdx.x;
    int v0 = (lane < SCAN_NB) ? g_bsum[lane] : 0;
    int i0 = v0;
    #pragma unroll
    for (int off = 1; off < 32; off <<= 1) {
        int t = __shfl_up_sync(0xffffffffu, i0, off);
        if (lane >= off) i0 += t;
    }
    int tot0 = __shfl_sync(0xffffffffu, i0, 31);
    if (lane < SCAN_NB) g_boff[lane] = i0 - v0;
    int j = 32 + lane;
    int v1 = (j < SCAN_NB) ? g_bsum[j] : 0;
    int i1 = v1;
    #pragma unroll
    for (int off = 1; off < 32; off <<= 1) {
        int t = __shfl_up_sync(0xffffffffu, i1, off);
        if (lane >= off) i1 += t;
    }
    if (j < SCAN_NB) g_boff[j] = tot0 + i1 - v1;
}

__global__ void k_scanC() {       // add offsets + self-loop slots
    int idx = blockIdx.x * blockDim.x + threadIdx.x;
    if (idx == 0) g_rowptr[N_NODES] = ET;
    if (idx >= N_NODES) return;
    int p = g_rowptr[idx] + g_boff[idx >> 10];
    g_rowptr[idx] = p;
    g_srcs[p] = idx;
    g_dsts[p] = idx;
}

// counting-sort scatter of real edges by dst; records inverse permutation
__global__ void k_scatter(const void* __restrict__ ei) {
    int e = blockIdx.x * blockDim.x + threadIdx.x;
    if (e >= N_EDGESC) return;
    int src = getIdx(ei, e);
    int dst = getIdx(ei, (long long)N_EDGESC + e);
    int p = g_rowptr[dst] + 1 + atomicAdd(&g_cnt[dst], 1);
    g_srcs[p] = src;
    g_dsts[p] = dst;
    g_slot[e] = p;
}

// permute attrs into CSR order: sequential reads x4 (MLP=4), scattered writes
__global__ void __launch_bounds__(256) k_permute(const float* __restrict__ ea) {
    int wid = (blockIdx.x * blockDim.x + threadIdx.x) >> 5;
    int nw  = (gridDim.x * blockDim.x) >> 5;
    int lane = threadIdx.x & 31;
    for (int e = wid * 4; e < N_EDGESC; e += nw * 4) {
        float v0 = ea[(long long)(e + 0) * FE + lane];
        float v1 = ea[(long long)(e + 1) * FE + lane];
        float v2 = ea[(long long)(e + 2) * FE + lane];
        float v3 = ea[(long long)(e + 3) * FE + lane];
        int s0 = g_slot[e + 0], s1 = g_slot[e + 1];
        int s2 = g_slot[e + 2], s3 = g_slot[e + 3];
        g_eas[(long long)s0 * FE + lane] = v0;
        g_eas[(long long)s1 * FE + lane] = v1;
        g_eas[(long long)s2 * FE + lane] = v2;
        g_eas[(long long)s3 * FE + lane] = v3;
    }
}

// self-loop attr = mean of incoming attrs (contiguous reads, dual accumulators)
__global__ void __launch_bounds__(256) k_loopcsr() {
    int wid = (blockIdx.x * blockDim.x + threadIdx.x) >> 5;
    if (wid >= N_NODES) return;
    int lane = threadIdx.x & 31;
    int beg = g_rowptr[wid], end = g_rowptr[wid + 1];
    float acc0 = 0.f, acc1 = 0.f;
    int i = beg + 1;
    for (; i + 1 < end; i += 2) {
        acc0 += g_eas[(long long)i * FE + lane];
        acc1 += g_eas[(long long)(i + 1) * FE + lane];
    }
    if (i < end) acc0 += g_eas[(long long)i * FE + lane];
    float d = (float)(end - beg - 1);
    g_eas[(long long)beg * FE + lane] = (acc0 + acc1) / fmaxf(d, 1.f);
}

// ---------------- node GEMMs: xl = h@Wl + bl, xr = h@Wr + br ------------------
__global__ void __launch_bounds__(128) k_xlxr(
    const float* __restrict__ x_ext, int hin_sel,
    const float* __restrict__ Wl, const float* __restrict__ bl,
    const float* __restrict__ Wr, const float* __restrict__ br) {
    const float* h = (hin_sel == 0) ? x_ext : (hin_sel == 1 ? g_hA : g_hB);
    __shared__ float shT[F][34];
    int j = threadIdx.x;
    int r0 = blockIdx.x * 32;
    #pragma unroll
    for (int r = 0; r < 32; r++) {
        int row = r0 + r;
        shT[j][r] = (row < N_NODES) ? h[(long long)row * F + j] : 0.f;
    }
    __syncthreads();
    u64 aL[16], aR[16];
    {
        u64 bl2 = pack2(bl[j], bl[j]);
        u64 br2 = pack2(br[j], br[j]);
        #pragma unroll
        for (int rp = 0; rp < 16; rp++) { aL[rp] = bl2; aR[rp] = br2; }
    }
    #pragma unroll 2
    for (int k = 0; k < F; k++) {
        float wl = Wl[k * F + j];
        float wr = Wr[k * F + j];
        u64 wl2 = pack2(wl, wl);
        u64 wr2 = pack2(wr, wr);
        #pragma unroll
        for (int rp = 0; rp < 16; rp++) {
            u64 hv2 = *(const u64*)&shT[k][2 * rp];
            aL[rp] = ffma2(hv2, wl2, aL[rp]);
            aR[rp] = ffma2(hv2, wr2, aR[rp]);
        }
    }
    #pragma unroll
    for (int rp = 0; rp < 16; rp++) {
        float2 l = unpack2(aL[rp]);
        float2 r = unpack2(aR[rp]);
        int row = r0 + 2 * rp;
        if (row < N_NODES)     { g_xl[(long long)row * F + j] = l.x; g_xr[(long long)row * F + j] = r.x; }
        if (row + 1 < N_NODES) { g_xl[(long long)(row + 1) * F + j] = l.y; g_xr[(long long)(row + 1) * F + j] = r.y; }
    }
}

// ---------------- per-edge attention score: deferred transpose reduce --------
// Warp-pair per 32-edge tile, column-split (64 cols/warp). Per edge each lane
// writes its partial contribution to smem (no per-edge shfl butterfly); after
// the loop one transposed 32-wide sum per lane pays the reduce latency ONCE per
// tile. Gather prefetch depth 4 keeps L2 latency covered.
__global__ void __launch_bounds__(128, 4) k_score(
    const float* __restrict__ We, const float* __restrict__ att) {
    __shared__ float2 sa[2][32][32];     // duplicated attr pairs, 16KB
    __shared__ float  sps[4][32][33];    // contributions [warp][edge][lane], 16.9KB
    __shared__ float  sp[4][32];         // per-warp per-edge totals
    int lane = threadIdx.x & 31;
    int wib  = threadIdx.x >> 5;        // 0..3
    int pair = wib >> 1;                // tile index within block
    int half = wib & 1;                 // column half
    int ntiles = (ET + 31) / 32;
    int tile = blockIdx.x * 2 + pair;
    long long base = (long long)tile * 32;
    int n = 0;
    if (tile < ntiles) n = (int)min((long long)32, (long long)ET - base);

    // cooperative attr staging: pair's warps do alternating rows
    for (int j2 = half; j2 < n; j2 += 2) {
        float a = g_eas[(base + j2) * FE + lane];
        sa[pair][j2][lane] = make_float2(a, a);
    }

    u64 w[FE];
    {
        const float* wp = We + 64 * half + 2 * lane;
        #pragma unroll
        for (int k = 0; k < FE; k++) {
            float2 wv = *(const float2*)(wp + k * F);
            w[k] = pack2(wv.x, wv.y);
        }
    }
    float2 at2 = *(const float2*)(att + 64 * half + 2 * lane);
    const float* xlb = g_xl + 64 * half + 2 * lane;
    const float* xrb = g_xr + 64 * half + 2 * lane;
    int src_l = (lane < n) ? g_srcs[base + lane] : 0;
    int dst_l = (lane < n) ? g_dsts[base + lane] : 0;
    __syncthreads();    // attrs staged for both warps of the pair

    if (n > 0) {
        float2 xl0, xr0, xl1, xr1, xl2, xr2, xl3, xr3;
        // prime depth-4 pipeline (lanes >= n hold idx 0 -> valid memory)
        {
            int s, d;
            s = __shfl_sync(0xffffffffu, src_l, 0);
            d = __shfl_sync(0xffffffffu, dst_l, 0);
            xl0 = *(const float2*)(xlb + (long long)s * F);
            xr0 = *(const float2*)(xrb + (long long)d * F);
            s = __shfl_sync(0xffffffffu, src_l, 1 < n ? 1 : 0);
            d = __shfl_sync(0xffffffffu, dst_l, 1 < n ? 1 : 0);
            xl1 = *(const float2*)(xlb + (long long)s * F);
            xr1 = *(const float2*)(xrb + (long long)d * F);
            s = __shfl_sync(0xffffffffu, src_l, 2 < n ? 2 : 0);
            d = __shfl_sync(0xffffffffu, dst_l, 2 < n ? 2 : 0);
            xl2 = *(const float2*)(xlb + (long long)s * F);
            xr2 = *(const float2*)(xrb + (long long)d * F);
            s = __shfl_sync(0xffffffffu, src_l, 3 < n ? 3 : 0);
            d = __shfl_sync(0xffffffffu, dst_l, 3 < n ? 3 : 0);
            xl3 = *(const float2*)(xlb + (long long)s * F);
            xr3 = *(const float2*)(xrb + (long long)d * F);
        }

#define SC_COMP(S)                                                          \
        {                                                                   \
            float2 u = make_float2(xl##S.x + xr##S.x, xl##S.y + xr##S.y);   \
            if (j + 4 < n) {                                                \
                int s_ = __shfl_sync(0xffffffffu, src_l, j + 4);            \
                int d_ = __shfl_sync(0xffffffffu, dst_l, j + 4);            \
                xl##S = *(const float2*)(xlb + (long long)s_ * F);          \
                xr##S = *(const float2*)(xrb + (long long)d_ * F);          \
            }                                                               \
            u64 acc0 = pack2(u.x, u.y);                                     \
            u64 acc1 = pack2(0.f, 0.f);                                     \
            const float4* sprow = (const float4*)sa[pair][j];               \
            _Pragma("unroll")                                               \
            for (int kk = 0; kk < FE / 2; kk++) {                           \
                float4 q = sprow[kk];                                       \
                acc0 = ffma2(pack2(q.x, q.y), w[2 * kk], acc0);             \
                acc1 = ffma2(pack2(q.z, q.w), w[2 * kk + 1], acc1);         \
            }                                                               \
            float2 e0 = unpack2(acc0), e1 = unpack2(acc1);                  \
            float c0v = e0.x + e1.x, c1v = e0.y + e1.y;                     \
            float t0 = c0v > 0.f ? c0v : SLOPE * c0v;                       \
            float t1 = c1v > 0.f ? c1v : SLOPE * c1v;                       \
            sps[wib][j][lane] = t0 * at2.x + t1 * at2.y;                    \
            j++;                                                            \
        }

        int j = 0;
        while (j < n) {
            SC_COMP(0); if (j >= n) break;
            SC_COMP(1); if (j >= n) break;
            SC_COMP(2); if (j >= n) break;
            SC_COMP(3);
        }
#undef SC_COMP
    }
    __syncwarp();
    // transposed reduce: lane l sums edge l's 32 contributions (pad-33, no conflicts)
    {
        float t0 = 0.f, t1 = 0.f;
        #pragma unroll 8
        for (int k = 0; k < 32; k += 2) {
            t0 += sps[wib][lane][k];
            t1 += sps[wib][lane][k + 1];
        }
        sp[wib][lane] = t0 + t1;
    }
    __syncthreads();
    if (half == 0 && lane < n)
        g_score[base + lane] = sp[wib][lane] + sp[wib + 1][lane];
}

// ---------------- softmax aggregation, two-pass (warp per node) --------------
__global__ void __launch_bounds__(256) k_agg(
    const float* __restrict__ bias, int hout_sel) {
    int wid = (blockIdx.x * blockDim.x + threadIdx.x) >> 5;
    if (wid >= N_NODES) return;
    float* hout = (hout_sel == 1) ? g_hB : g_hA;
    int lane = threadIdx.x & 31;
    int beg = g_rowptr[wid], end = g_rowptr[wid + 1];

    float m = -3.0e38f;
    for (int t = beg + lane; t < end; t += 32) m = fmaxf(m, g_score[t]);
    #pragma unroll
    for (int off = 16; off; off >>= 1) m = fmaxf(m, __shfl_xor_sync(0xffffffffu, m, off));
    float den = 0.f;
    for (int t = beg + lane; t < end; t += 32) den += __expf(g_score[t] - m);
    #pragma unroll
    for (int off = 16; off; off >>= 1) den += __shfl_xor_sync(0xffffffffu, den, off);
    float inv = 1.f / den;

    float4 a0 = make_float4(0.f, 0.f, 0.f, 0.f), a1 = a0, a2 = a0, a3 = a0;
    for (int t = beg; t < end; t += 32) {
        int idx = t + lane;
        bool ok = idx < end;
        float pe = ok ? __expf(g_score[idx] - m) : 0.f;
        int   sr = ok ? g_srcs[idx] : 0;
        int cnt = min(32, end - t);
        int j = 0;
        for (; j + 4 <= cnt; j += 4) {
            float p0 = __shfl_sync(0xffffffffu, pe, j);
            float p1 = __shfl_sync(0xffffffffu, pe, j + 1);
            float p2 = __shfl_sync(0xffffffffu, pe, j + 2);
            float p3 = __shfl_sync(0xffffffffu, pe, j + 3);
            int s0 = __shfl_sync(0xffffffffu, sr, j);
            int s1 = __shfl_sync(0xffffffffu, sr, j + 1);
            int s2 = __shfl_sync(0xffffffffu, sr, j + 2);
            int s3 = __shfl_sync(0xffffffffu, sr, j + 3);
            float4 x0 = *(const float4*)(g_xl + (long long)s0 * F + 4 * lane);
            float4 x1 = *(const float4*)(g_xl + (long long)s1 * F + 4 * lane);
            float4 x2 = *(const float4*)(g_xl + (long long)s2 * F + 4 * lane);
            float4 x3 = *(const float4*)(g_xl + (long long)s3 * F + 4 * lane);
            a0.x += p0 * x0.x; a0.y += p0 * x0.y; a0.z += p0 * x0.z; a0.w += p0 * x0.w;
            a1.x += p1 * x1.x; a1.y += p1 * x1.y; a1.z += p1 * x1.z; a1.w += p1 * x1.w;
            a2.x += p2 * x2.x; a2.y += p2 * x2.y; a2.z += p2 * x2.z; a2.w += p2 * x2.w;
            a3.x += p3 * x3.x; a3.y += p3 * x3.y; a3.z += p3 * x3.z; a3.w += p3 * x3.w;
        }
        for (; j < cnt; j++) {
            float pj = __shfl_sync(0xffffffffu, pe, j);
            int   sj = __shfl_sync(0xffffffffu, sr, j);
            float4 xj = *(const float4*)(g_xl + (long long)sj * F + 4 * lane);
            a0.x += pj * xj.x; a0.y += pj * xj.y; a0.z += pj * xj.z; a0.w += pj * xj.w;
        }
    }
    float4 bi = *(const float4*)(bias + 4 * lane);
    float4 o;
    o.x = fmaxf((a0.x + a1.x + a2.x + a3.x) * inv + bi.x, 0.f);
    o.y = fmaxf((a0.y + a1.y + a2.y + a3.y) * inv + bi.y, 0.f);
    o.z = fmaxf((a0.z + a1.z + a2.z + a3.z) * inv + bi.z, 0.f);
    o.w = fmaxf((a0.w + a1.w + a2.w + a3.w) * inv + bi.w, 0.f);
    *(float4*)(hout + (long long)wid * F + 4 * lane) = o;
}

// ---------------- pool + classifier ----------------------------------------
__global__ void k_gptr(const void* __restrict__ batch) {
    int g = blockIdx.x * blockDim.x + threadIdx.x;
    if (g > NG) return;
    int lo = 0, hi = N_NODES;
    while (lo < hi) {
        int mid = (lo + hi) >> 1;
        if (getIdx(batch, mid) < g) lo = mid + 1; else hi = mid;
    }
    g_gptr[g] = lo;
}

__global__ void __launch_bounds__(128) k_poolg() {
    int g = blockIdx.x;
    int j = threadIdx.x;
    int b = g_gptr[g], e = g_gptr[g + 1];
    float acc = 0.f;
    for (int v = b; v < e; v++) acc += g_hA[(long long)v * F + j];
    float inv = 1.f / fmaxf((float)(e - b), 1.f);
    g_pool[g * F + j] = acc * inv;
}

__global__ void k_final(const float* __restrict__ lw, const float* __restrict__ lb,
                        float* __restrict__ out) {
    int t = blockIdx.x * blockDim.x + threadIdx.x;
    if (t >= NG * NC) return;
    int g = t / NC, cls = t % NC;
    float acc = lb[cls];
    #pragma unroll 8
    for (int c = 0; c < F; c++)
        acc += g_pool[g * F + c] * lw[c * NC + cls];
    out[t] = acc;
}

// ---------------- host -------------------------------------------------------
extern "C" void kernel_launch(void* const* d_in, const int* in_sizes, int n_in,
                              void* d_out, int out_size) {
    (void)in_sizes; (void)n_in; (void)out_size;
    const float* x     = (const float*)d_in[0];
    const void*  ei    = d_in[1];
    const void*  batch = d_in[2];
    // d_in[3] = dropout (identity in eval)
    const float* ea   = (const float*)d_in[4];
    const float* Wl   = (const float*)d_in[5];
    const float* bl   = (const float*)d_in[6];
    const float* Wr   = (const float*)d_in[7];
    const float* br   = (const float*)d_in[8];
    const float* We   = (const float*)d_in[9];
    const float* att  = (const float*)d_in[10];
    const float* bias = (const float*)d_in[11];
    const float* lw   = (const float*)d_in[12];
    const float* lb   = (const float*)d_in[13];
    float* out = (float*)d_out;

    k_probe_zero<<<(N_NODES + 255) / 256, 256>>>(ei);
    k_deg<<<(N_EDGESC + 255) / 256, 256>>>(ei);
    k_scanA<<<SCAN_NB, 1024>>>();
    k_scanB<<<1, 32>>>();
    k_scanC<<<(N_NODES + 255) / 256, 256>>>();
    k_scatter<<<(N_EDGESC + 255) / 256, 256>>>(ei);
    k_permute<<<2048, 256>>>(ea);
    k_loopcsr<<<(N_NODES * 32 + 255) / 256, 256>>>();

    int ntiles = (ET + 31) / 32;
    int nblocks = (ntiles + 1) / 2;       // 2 tiles (4 warps) per block
    for (int l = 0; l < 3; l++) {
        int hin  = l;                 // 0: x, 1: hA, 2: hB
        int hout = (l == 1) ? 1 : 0;  // layer0 -> hA, layer1 -> hB, layer2 -> hA
        k_xlxr<<<(N_NODES + 31) / 32, 128>>>(x, hin,
                                             Wl + (size_t)l * F * F, bl + (size_t)l * F,
                                             Wr + (size_t)l * F * F, br + (size_t)l * F);
        k_score<<<nblocks, 128>>>(We + (size_t)l * FE * F, att + (size_t)l * F);
        k_agg<<<(N_NODES * 32 + 255) / 256, 256>>>(bias + (size_t)l * F, hout);
    }

    k_gptr<<<3, 256>>>(batch);
    k_poolg<<<NG, 128>>>();
    k_final<<<(NG * NC + 127) / 128, 128>>>(lw, lb, out);
}